// round 6
// baseline (speedup 1.0000x reference)
#include <cuda_runtime.h>
#include <cstdint>

#define BATCH 8
#define NT 1024
#define DIM 768
#define NH 12
#define HD 64
#define SCALE 0.125f
#define NBH (BATCH * NH)

// scratch (allocation-free rule: __device__ globals)
__device__ float g_q[NBH * NT * HD];
__device__ float g_k[NBH * NT * HD];
__device__ float g_vt[NBH * HD * NT];             // V transposed: [bh][d][t]
__device__ float g_x[BATCH * NT * DIM];
__device__ float g_tf[BATCH * NT * DIM];          // tf32-rounded tfeat
__device__ float g_w[4 * DIM * DIM];              // tf32-rounded wq,wk,wv,wp
__device__ float g_rinv[NBH * NT];                // 1 / rowsum of exp scores

// ---------------------------------------------------------------------------
// helpers
// ---------------------------------------------------------------------------
__device__ __forceinline__ uint32_t f2tf(float x) {
    uint32_t r;
    asm("cvt.rna.tf32.f32 %0, %1;" : "=r"(r) : "f"(x));
    return r;
}
__device__ __forceinline__ float round_tf(float x) { return __uint_as_float(f2tf(x)); }

__device__ __forceinline__ void cp16(uint32_t s, const void* g) {
    asm volatile("cp.async.cg.shared.global [%0], [%1], 16;" :: "r"(s), "l"(g));
}
__device__ __forceinline__ void cp_commit() { asm volatile("cp.async.commit_group;"); }
template <int N> __device__ __forceinline__ void cp_wait() {
    asm volatile("cp.async.wait_group %0;" :: "n"(N));
}

__device__ __forceinline__ void mma8(float* c,
                                     uint32_t a0, uint32_t a1, uint32_t a2, uint32_t a3,
                                     uint32_t b0, uint32_t b1) {
    asm volatile(
        "mma.sync.aligned.m16n8k8.row.col.f32.tf32.tf32.f32 "
        "{%0,%1,%2,%3},{%4,%5,%6,%7},{%8,%9},{%0,%1,%2,%3};"
        : "+f"(c[0]), "+f"(c[1]), "+f"(c[2]), "+f"(c[3])
        : "r"(a0), "r"(a1), "r"(a2), "r"(a3), "r"(b0), "r"(b1));
}

// 128x128 block, 8 warps as 2x4 (warp tile 64x32) -- used by qkv/proj
template <int STRIDE, int NKS>
__device__ __forceinline__ void compute_tiles(const uint32_t* __restrict__ As,
                                              const uint32_t* __restrict__ Bs,
                                              int wm, int wn, int lane,
                                              float acc[4][4][4]) {
#pragma unroll
    for (int ks = 0; ks < NKS; ++ks) {
        const int col = ks * 8 + (lane & 3);
        uint32_t a[4][4], b[4][2];
#pragma unroll
        for (int mt = 0; mt < 4; ++mt) {
            int r = wm * 64 + mt * 16 + (lane >> 2);
            a[mt][0] = As[r * STRIDE + col];
            a[mt][1] = As[(r + 8) * STRIDE + col];
            a[mt][2] = As[r * STRIDE + col + 4];
            a[mt][3] = As[(r + 8) * STRIDE + col + 4];
        }
#pragma unroll
        for (int nt = 0; nt < 4; ++nt) {
            int n = wn * 32 + nt * 8 + (lane >> 2);
            b[nt][0] = Bs[n * STRIDE + col];
            b[nt][1] = Bs[n * STRIDE + col + 4];
        }
#pragma unroll
        for (int mt = 0; mt < 4; ++mt)
#pragma unroll
            for (int nt = 0; nt < 4; ++nt)
                mma8(acc[mt][nt], a[mt][0], a[mt][1], a[mt][2], a[mt][3],
                     b[nt][0], b[nt][1]);
    }
}

// 64x64 tile, 8 warps as 2x4 (warp tile 32x16), operands stride 68, K=64
__device__ __forceinline__ void compute_s64(const uint32_t* __restrict__ As,
                                            const uint32_t* __restrict__ Bs,
                                            int wm, int wn, int lane,
                                            float acc[2][2][4]) {
#pragma unroll
    for (int ks = 0; ks < 8; ++ks) {
        const int col = ks * 8 + (lane & 3);
        uint32_t a[2][4], b[2][2];
#pragma unroll
        for (int mt = 0; mt < 2; ++mt) {
            int r = wm * 32 + mt * 16 + (lane >> 2);
            a[mt][0] = As[r * 68 + col];
            a[mt][1] = As[(r + 8) * 68 + col];
            a[mt][2] = As[r * 68 + col + 4];
            a[mt][3] = As[(r + 8) * 68 + col + 4];
        }
#pragma unroll
        for (int nt = 0; nt < 2; ++nt) {
            int n = wn * 16 + nt * 8 + (lane >> 2);
            b[nt][0] = Bs[n * 68 + col];
            b[nt][1] = Bs[n * 68 + col + 4];
        }
#pragma unroll
        for (int mt = 0; mt < 2; ++mt)
#pragma unroll
            for (int nt = 0; nt < 2; ++nt)
                mma8(acc[mt][nt], a[mt][0], a[mt][1], a[mt][2], a[mt][3],
                     b[nt][0], b[nt][1]);
    }
}

// ---------------------------------------------------------------------------
// 0) tf32 pre-rounding, one launch: grid.y selects tensor
// ---------------------------------------------------------------------------
__global__ void round_all_kernel(const float* __restrict__ tfeat,
                                 const float* __restrict__ wq,
                                 const float* __restrict__ wk,
                                 const float* __restrict__ wv,
                                 const float* __restrict__ wp) {
    const int y = blockIdx.y;
    const float* src;
    float* dst;
    int n4;
    if (y == 0) { src = tfeat; dst = g_tf; n4 = BATCH * NT * DIM / 4; }
    else {
        src = (y == 1) ? wq : (y == 2) ? wk : (y == 3) ? wv : wp;
        dst = g_w + (size_t)(y - 1) * DIM * DIM;
        n4 = DIM * DIM / 4;
    }
    for (int i = blockIdx.x * blockDim.x + threadIdx.x; i < n4;
         i += gridDim.x * blockDim.x) {
        float4 v = ((const float4*)src)[i];
        v.x = round_tf(v.x); v.y = round_tf(v.y);
        v.z = round_tf(v.z); v.w = round_tf(v.w);
        ((float4*)dst)[i] = v;
    }
}

// ---------------------------------------------------------------------------
// 1) QKV projection, cp.async double-buffered. grid (6, 64, 3).
//    V (z==2) epilogue transposes through smem -> g_vt[bh][d][t].
// ---------------------------------------------------------------------------
__global__ __launch_bounds__(256, 2) void qkv_gemm_kernel(
    const float* __restrict__ bq, const float* __restrict__ bk,
    const float* __restrict__ bv)
{
    extern __shared__ uint32_t sm[];
    const uint32_t sbase = (uint32_t)__cvta_generic_to_shared(sm);

    const int z = blockIdx.z;
    const float* A = g_tf;
    const float* W = g_w + (size_t)z * DIM * DIM;
    const float* bias = (z == 0) ? bq : (z == 1) ? bk : bv;

    const int tid = threadIdx.x;
    const int lane = tid & 31;
    const int wid = tid >> 5;
    const int wm = wid >> 2, wn = wid & 3;
    const int m0 = blockIdx.y * 128;
    const int n0 = blockIdx.x * 128;

    const int srow = tid >> 3;
    const int skq = (tid & 7) << 2;

    auto stage = [&](int buf, int k0) {
        uint32_t aofs = sbase + (uint32_t)(buf * 4608) * 4;
        uint32_t bofs = sbase + (uint32_t)(9216 + buf * 4608) * 4;
#pragma unroll
        for (int u = 0; u < 4; ++u) {
            int row = srow + u * 32;
            cp16(aofs + (uint32_t)(row * 36 + skq) * 4, &A[(size_t)(m0 + row) * DIM + k0 + skq]);
            cp16(bofs + (uint32_t)(row * 36 + skq) * 4, &W[(size_t)(n0 + row) * DIM + k0 + skq]);
        }
        cp_commit();
    };

    float acc[4][4][4] = {};
    stage(0, 0);
    for (int kt = 0; kt < 24; ++kt) {
        if (kt + 1 < 24) { stage((kt + 1) & 1, (kt + 1) * 32); cp_wait<1>(); }
        else cp_wait<0>();
        __syncthreads();
        const uint32_t* As = sm + (kt & 1) * 4608;
        const uint32_t* Bs = sm + 9216 + (kt & 1) * 4608;
        compute_tiles<36, 4>(As, Bs, wm, wn, lane, acc);
        __syncthreads();
    }

    if (z < 2) {
        float* out = (z == 0) ? g_q : g_k;
#pragma unroll
        for (int mt = 0; mt < 4; ++mt) {
            int row = m0 + wm * 64 + mt * 16 + (lane >> 2);
            int b0i = row >> 10, t0 = row & 1023;
#pragma unroll
            for (int nt = 0; nt < 4; ++nt) {
                int col = n0 + wn * 32 + nt * 8 + ((lane & 3) << 1);
                int h = col >> 6, d = col & 63;
                float bx = bias[col], by = bias[col + 1];
                float2 lo = make_float2(round_tf(acc[mt][nt][0] + bx), round_tf(acc[mt][nt][1] + by));
                float2 hi = make_float2(round_tf(acc[mt][nt][2] + bx), round_tf(acc[mt][nt][3] + by));
                *(float2*)&out[((size_t)(b0i * NH + h) * NT + t0) * HD + d] = lo;
                *(float2*)&out[((size_t)(b0i * NH + h) * NT + t0 + 8) * HD + d] = hi;
            }
        }
    } else {
        // transpose through smem: T[t_local][d_local], stride 133
        float* T = (float*)sm;
#pragma unroll
        for (int mt = 0; mt < 4; ++mt) {
            int lr = wm * 64 + mt * 16 + (lane >> 2);
#pragma unroll
            for (int nt = 0; nt < 4; ++nt) {
                int lc = wn * 32 + nt * 8 + ((lane & 3) << 1);
                float bx = bias[n0 + lc], by = bias[n0 + lc + 1];
                T[lr * 133 + lc]       = round_tf(acc[mt][nt][0] + bx);
                T[lr * 133 + lc + 1]   = round_tf(acc[mt][nt][1] + by);
                T[(lr + 8) * 133 + lc]     = round_tf(acc[mt][nt][2] + bx);
                T[(lr + 8) * 133 + lc + 1] = round_tf(acc[mt][nt][3] + by);
            }
        }
        __syncthreads();
        const int b0i = m0 >> 10;
        const int t00 = m0 & 1023;
#pragma unroll
        for (int u = 0; u < 16; ++u) {
            int idx = tid + u * 256;
            int dcol = idx >> 5;
            int tq = (idx & 31) << 2;
            float4 v = make_float4(T[(tq + 0) * 133 + dcol], T[(tq + 1) * 133 + dcol],
                                   T[(tq + 2) * 133 + dcol], T[(tq + 3) * 133 + dcol]);
            int h = (n0 + dcol) >> 6, d = (n0 + dcol) & 63;
            *(float4*)&g_vt[((size_t)(b0i * NH + h) * HD + d) * NT + t00 + tq] = v;
        }
    }
}

// ---------------------------------------------------------------------------
// 2) rowsum: rinv[row] = 1 / sum_j exp(S[row][j]*SCALE). grid (16, 96).
//    M=64, coltile 64, K double-buffered. smem 13056 w = 52224 B -> 4 blk/SM.
// ---------------------------------------------------------------------------
__global__ __launch_bounds__(256, 4) void rowsum_kernel()
{
    extern __shared__ uint32_t sm[];
    __shared__ float redsum[4][64];
    const uint32_t sbase = (uint32_t)__cvta_generic_to_shared(sm);

    const int tid = threadIdx.x;
    const int lane = tid & 31;
    const int wid = tid >> 5;
    const int wm = wid >> 2, wn = wid & 3;
    const int m0 = blockIdx.x * 64;
    const int bh = blockIdx.y;

    const float* Q = g_q + (size_t)bh * NT * HD;
    const float* K = g_k + (size_t)bh * NT * HD;

    auto stageK = [&](int buf, int c0) {
        uint32_t kofs = sbase + (uint32_t)(4352 + buf * 4352) * 4;
#pragma unroll
        for (int u = 0; u < 4; ++u) {
            int idx = tid + u * 256;
            int row = idx >> 4;
            int kq = (idx & 15) << 2;
            cp16(kofs + (uint32_t)(row * 68 + kq) * 4, &K[(size_t)(c0 + row) * HD + kq]);
        }
    };

    // stage Q + K0
#pragma unroll
    for (int u = 0; u < 4; ++u) {
        int idx = tid + u * 256;
        int row = idx >> 4;
        int kq = (idx & 15) << 2;
        cp16(sbase + (uint32_t)(row * 68 + kq) * 4, &Q[(size_t)(m0 + row) * HD + kq]);
    }
    stageK(0, 0);
    cp_commit();
    cp_wait<0>();
    __syncthreads();

    float rsum[2][2] = {};
    for (int ct = 0; ct < 16; ++ct) {
        if (ct + 1 < 16) { stageK((ct + 1) & 1, (ct + 1) * 64); cp_commit(); }
        float acc[2][2][4] = {};
        compute_s64(sm, sm + 4352 + (ct & 1) * 4352, wm, wn, lane, acc);
#pragma unroll
        for (int mt = 0; mt < 2; ++mt)
#pragma unroll
            for (int nt = 0; nt < 2; ++nt) {
                rsum[mt][0] += __expf(acc[mt][nt][0] * SCALE) + __expf(acc[mt][nt][1] * SCALE);
                rsum[mt][1] += __expf(acc[mt][nt][2] * SCALE) + __expf(acc[mt][nt][3] * SCALE);
            }
        if (ct + 1 < 16) cp_wait<0>();
        __syncthreads();
    }
#pragma unroll
    for (int off = 1; off < 4; off <<= 1)
#pragma unroll
        for (int mt = 0; mt < 2; ++mt) {
            rsum[mt][0] += __shfl_xor_sync(0xffffffffu, rsum[mt][0], off);
            rsum[mt][1] += __shfl_xor_sync(0xffffffffu, rsum[mt][1], off);
        }
    if ((lane & 3) == 0) {
#pragma unroll
        for (int mt = 0; mt < 2; ++mt) {
            int r = wm * 32 + mt * 16 + (lane >> 2);
            redsum[wn][r] = rsum[mt][0];
            redsum[wn][r + 8] = rsum[mt][1];
        }
    }
    __syncthreads();
    if (tid < 64) {
        float s = redsum[0][tid] + redsum[1][tid] + redsum[2][tid] + redsum[3][tid];
        g_rinv[(size_t)bh * NT + m0 + tid] = 1.0f / s;
    }
}

// ---------------------------------------------------------------------------
// 3) fused: recompute S, normalize, write final attn once, PV from smem.
//    grid (16, 96). M=64, coltile 64. smem 26112 w = 104448 B -> 2 blk/SM.
//    words: Qs[0,4352) K[4352+buf*4352) V[13056+buf*4352) Ps[21760,26112)
// ---------------------------------------------------------------------------
__global__ __launch_bounds__(256, 2) void attn_fused_kernel(float* __restrict__ attn)
{
    extern __shared__ uint32_t sm[];
    __shared__ float rinv_s[64];
    const uint32_t sbase = (uint32_t)__cvta_generic_to_shared(sm);

    uint32_t* const Ps = sm + 21760;

    const int tid = threadIdx.x;
    const int lane = tid & 31;
    const int wid = tid >> 5;
    const int wm = wid >> 2, wn = wid & 3;
    const int m0 = blockIdx.x * 64;
    const int bh = blockIdx.y;

    const float* Q = g_q + (size_t)bh * NT * HD;
    const float* K = g_k + (size_t)bh * NT * HD;
    const float* VT = g_vt + (size_t)bh * HD * NT;

    if (tid < 64) rinv_s[tid] = g_rinv[(size_t)bh * NT + m0 + tid];

    auto stageK = [&](int buf, int c0) {
        uint32_t kofs = sbase + (uint32_t)(4352 + buf * 4352) * 4;
#pragma unroll
        for (int u = 0; u < 4; ++u) {
            int idx = tid + u * 256;
            int row = idx >> 4;
            int kq = (idx & 15) << 2;
            cp16(kofs + (uint32_t)(row * 68 + kq) * 4, &K[(size_t)(c0 + row) * HD + kq]);
        }
    };
    auto stageV = [&](int buf, int c0) {
        uint32_t vofs = sbase + (uint32_t)(13056 + buf * 4352) * 4;
#pragma unroll
        for (int u = 0; u < 4; ++u) {
            int idx = tid + u * 256;
            int d = idx >> 4;
            int tq = (idx & 15) << 2;
            cp16(vofs + (uint32_t)(d * 68 + tq) * 4, &VT[(size_t)d * NT + c0 + tq]);
        }
    };

    // stage Q + K0 + V0
#pragma unroll
    for (int u = 0; u < 4; ++u) {
        int idx = tid + u * 256;
        int row = idx >> 4;
        int kq = (idx & 15) << 2;
        cp16(sbase + (uint32_t)(row * 68 + kq) * 4, &Q[(size_t)(m0 + row) * HD + kq]);
    }
    stageK(0, 0);
    stageV(0, 0);
    cp_commit();
    cp_wait<0>();
    __syncthreads();

    float rv[2][2];
#pragma unroll
    for (int mt = 0; mt < 2; ++mt) {
        rv[mt][0] = rinv_s[wm * 32 + mt * 16 + (lane >> 2)];
        rv[mt][1] = rinv_s[wm * 32 + mt * 16 + (lane >> 2) + 8];
    }

    float acc_o[2][2][4] = {};
    float* ap = attn + (size_t)bh * NT * NT;

    for (int ct = 0; ct < 16; ++ct) {
        const int col0 = ct * 64;
        if (ct + 1 < 16) {
            stageK((ct + 1) & 1, (ct + 1) * 64);
            stageV((ct + 1) & 1, (ct + 1) * 64);
            cp_commit();
        }

        // S = Q K^T (this tile)
        float acc_s[2][2][4] = {};
        compute_s64(sm, sm + 4352 + (ct & 1) * 4352, wm, wn, lane, acc_s);

        // exp, normalize, write final attn, stage P (tf32) into Ps
#pragma unroll
        for (int mt = 0; mt < 2; ++mt) {
            int lr = wm * 32 + mt * 16 + (lane >> 2);
#pragma unroll
            for (int nt = 0; nt < 2; ++nt) {
                int lc = wn * 16 + nt * 8 + ((lane & 3) << 1);
                float e0 = __expf(acc_s[mt][nt][0] * SCALE) * rv[mt][0];
                float e1 = __expf(acc_s[mt][nt][1] * SCALE) * rv[mt][0];
                float e2 = __expf(acc_s[mt][nt][2] * SCALE) * rv[mt][1];
                float e3 = __expf(acc_s[mt][nt][3] * SCALE) * rv[mt][1];
                __stcs((float2*)&ap[(size_t)(m0 + lr) * NT + col0 + lc], make_float2(e0, e1));
                __stcs((float2*)&ap[(size_t)(m0 + lr + 8) * NT + col0 + lc], make_float2(e2, e3));
                *(uint2*)&Ps[lr * 68 + lc] = make_uint2(f2tf(e0), f2tf(e1));
                *(uint2*)&Ps[(lr + 8) * 68 + lc] = make_uint2(f2tf(e2), f2tf(e3));
            }
        }
        __syncthreads();                       // Ps visible to all warps

        // O += P V  (Ps [64m][68], Vs [64d][68] with k = t-local)
        const uint32_t* Vs = sm + 13056 + (ct & 1) * 4352;
        compute_s64(Ps, Vs, wm, wn, lane, acc_o);

        if (ct + 1 < 16) cp_wait<0>();
        __syncthreads();                       // Ps reusable; next K/V ready
    }

    const int b = bh / NH, h = bh % NH;
#pragma unroll
    for (int mt = 0; mt < 2; ++mt) {
        int row = m0 + wm * 32 + mt * 16 + (lane >> 2);
#pragma unroll
        for (int nt = 0; nt < 2; ++nt) {
            int d = wn * 16 + nt * 8 + ((lane & 3) << 1);
            *(float2*)&g_x[((size_t)b * NT + row) * DIM + h * HD + d] =
                make_float2(round_tf(acc_o[mt][nt][0]), round_tf(acc_o[mt][nt][1]));
            *(float2*)&g_x[((size_t)b * NT + row + 8) * DIM + h * HD + d] =
                make_float2(round_tf(acc_o[mt][nt][2]), round_tf(acc_o[mt][nt][3]));
        }
    }
}

// ---------------------------------------------------------------------------
// 4) output projection, cp.async double-buffered. grid (6, 64).
// ---------------------------------------------------------------------------
__global__ __launch_bounds__(256, 2) void proj_gemm_kernel(
    const float* __restrict__ bias, float* __restrict__ out)
{
    extern __shared__ uint32_t sm[];
    const uint32_t sbase = (uint32_t)__cvta_generic_to_shared(sm);

    const float* A = g_x;
    const float* W = g_w + (size_t)3 * DIM * DIM;

    const int tid = threadIdx.x;
    const int lane = tid & 31;
    const int wid = tid >> 5;
    const int wm = wid >> 2, wn = wid & 3;
    const int m0 = blockIdx.y * 128;
    const int n0 = blockIdx.x * 128;

    const int srow = tid >> 3;
    const int skq = (tid & 7) << 2;

    auto stage = [&](int buf, int k0) {
        uint32_t aofs = sbase + (uint32_t)(buf * 4608) * 4;
        uint32_t bofs = sbase + (uint32_t)(9216 + buf * 4608) * 4;
#pragma unroll
        for (int u = 0; u < 4; ++u) {
            int row = srow + u * 32;
            cp16(aofs + (uint32_t)(row * 36 + skq) * 4, &A[(size_t)(m0 + row) * DIM + k0 + skq]);
            cp16(bofs + (uint32_t)(row * 36 + skq) * 4, &W[(size_t)(n0 + row) * DIM + k0 + skq]);
        }
        cp_commit();
    };

    float acc[4][4][4] = {};
    stage(0, 0);
    for (int kt = 0; kt < 24; ++kt) {
        if (kt + 1 < 24) { stage((kt + 1) & 1, (kt + 1) * 32); cp_wait<1>(); }
        else cp_wait<0>();
        __syncthreads();
        const uint32_t* As = sm + (kt & 1) * 4608;
        const uint32_t* Bs = sm + 9216 + (kt & 1) * 4608;
        compute_tiles<36, 4>(As, Bs, wm, wn, lane, acc);
        __syncthreads();
    }

#pragma unroll
    for (int mt = 0; mt < 4; ++mt) {
        int row = m0 + wm * 64 + mt * 16 + (lane >> 2);
#pragma unroll
        for (int nt = 0; nt < 4; ++nt) {
            int col = n0 + wn * 32 + nt * 8 + ((lane & 3) << 1);
            float bx = bias[col], by = bias[col + 1];
            *(float2*)&out[(size_t)row * DIM + col] =
                make_float2(acc[mt][nt][0] + bx, acc[mt][nt][1] + by);
            *(float2*)&out[(size_t)(row + 8) * DIM + col] =
                make_float2(acc[mt][nt][2] + bx, acc[mt][nt][3] + by);
        }
    }
}

// ---------------------------------------------------------------------------

extern "C" void kernel_launch(void* const* d_in, const int* in_sizes, int n_in,
                              void* d_out, int out_size)
{
    const float* tfeat = (const float*)d_in[0];
    const float* wq = (const float*)d_in[1];
    const float* bq = (const float*)d_in[2];
    const float* wk = (const float*)d_in[3];
    const float* bk = (const float*)d_in[4];
    const float* wv = (const float*)d_in[5];
    const float* bv = (const float*)d_in[6];
    const float* wp = (const float*)d_in[7];
    const float* bp = (const float*)d_in[8];

    float* xout = (float*)d_out;
    float* attn_out = (float*)d_out + (size_t)BATCH * NT * DIM;

    round_all_kernel<<<dim3(1024, 5), 256>>>(tfeat, wq, wk, wv, wp);

    cudaFuncSetAttribute(qkv_gemm_kernel, cudaFuncAttributeMaxDynamicSharedMemorySize, 73728);
    cudaFuncSetAttribute(rowsum_kernel, cudaFuncAttributeMaxDynamicSharedMemorySize, 52224);
    cudaFuncSetAttribute(attn_fused_kernel, cudaFuncAttributeMaxDynamicSharedMemorySize, 104448);
    cudaFuncSetAttribute(proj_gemm_kernel, cudaFuncAttributeMaxDynamicSharedMemorySize, 73728);

    qkv_gemm_kernel<<<dim3(DIM / 128, (BATCH * NT) / 128, 3), 256, 73728>>>(bq, bk, bv);
    rowsum_kernel<<<dim3(NT / 64, NBH), 256, 52224>>>();
    attn_fused_kernel<<<dim3(NT / 64, NBH), 256, 104448>>>(attn_out);
    proj_gemm_kernel<<<dim3(DIM / 128, (BATCH * NT) / 128), 256, 73728>>>(bp, xout);
}

// round 7
// speedup vs baseline: 1.1332x; 1.1332x over previous
#include <cuda_runtime.h>
#include <cstdint>

#define BATCH 8
#define NT 1024
#define DIM 768
#define NH 12
#define HD 64
#define SCALE 0.125f
#define NBH (BATCH * NH)

// scratch (allocation-free rule: __device__ globals)
__device__ float g_q[NBH * NT * HD];
__device__ float g_k[NBH * NT * HD];
__device__ float g_v[NBH * NT * HD];
__device__ float g_x[BATCH * NT * DIM];
__device__ float g_tf[BATCH * NT * DIM];          // tf32-rounded tfeat
__device__ float g_w[4 * DIM * DIM];              // tf32-rounded wq,wk,wv,wp
__device__ float g_psum[(size_t)NBH * NT * 8];

// ---------------------------------------------------------------------------
// helpers
// ---------------------------------------------------------------------------
__device__ __forceinline__ uint32_t f2tf(float x) {
    uint32_t r;
    asm("cvt.rna.tf32.f32 %0, %1;" : "=r"(r) : "f"(x));
    return r;
}
__device__ __forceinline__ float round_tf(float x) { return __uint_as_float(f2tf(x)); }

__device__ __forceinline__ void cp16(uint32_t s, const void* g) {
    asm volatile("cp.async.cg.shared.global [%0], [%1], 16;" :: "r"(s), "l"(g));
}
__device__ __forceinline__ void cp4(uint32_t s, const void* g) {
    asm volatile("cp.async.ca.shared.global [%0], [%1], 4;" :: "r"(s), "l"(g));
}
__device__ __forceinline__ void cp_commit() { asm volatile("cp.async.commit_group;"); }
template <int N> __device__ __forceinline__ void cp_wait() {
    asm volatile("cp.async.wait_group %0;" :: "n"(N));
}

__device__ __forceinline__ void mma8(float* c,
                                     uint32_t a0, uint32_t a1, uint32_t a2, uint32_t a3,
                                     uint32_t b0, uint32_t b1) {
    asm volatile(
        "mma.sync.aligned.m16n8k8.row.col.f32.tf32.tf32.f32 "
        "{%0,%1,%2,%3},{%4,%5,%6,%7},{%8,%9},{%0,%1,%2,%3};"
        : "+f"(c[0]), "+f"(c[1]), "+f"(c[2]), "+f"(c[3])
        : "r"(a0), "r"(a1), "r"(a2), "r"(a3), "r"(b0), "r"(b1));
}

// 128x128 block, 8 warps as 2x4 (warp tile 64x32)
template <int STRIDE, int NKS>
__device__ __forceinline__ void compute_tiles(const uint32_t* __restrict__ As,
                                              const uint32_t* __restrict__ Bs,
                                              int wm, int wn, int lane,
                                              float acc[4][4][4]) {
#pragma unroll
    for (int ks = 0; ks < NKS; ++ks) {
        const int col = ks * 8 + (lane & 3);
        uint32_t a[4][4], b[4][2];
#pragma unroll
        for (int mt = 0; mt < 4; ++mt) {
            int r = wm * 64 + mt * 16 + (lane >> 2);
            a[mt][0] = As[r * STRIDE + col];
            a[mt][1] = As[(r + 8) * STRIDE + col];
            a[mt][2] = As[r * STRIDE + col + 4];
            a[mt][3] = As[(r + 8) * STRIDE + col + 4];
        }
#pragma unroll
        for (int nt = 0; nt < 4; ++nt) {
            int n = wn * 32 + nt * 8 + (lane >> 2);
            b[nt][0] = Bs[n * STRIDE + col];
            b[nt][1] = Bs[n * STRIDE + col + 4];
        }
#pragma unroll
        for (int mt = 0; mt < 4; ++mt)
#pragma unroll
            for (int nt = 0; nt < 4; ++nt)
                mma8(acc[mt][nt], a[mt][0], a[mt][1], a[mt][2], a[mt][3],
                     b[nt][0], b[nt][1]);
    }
}

// ---------------------------------------------------------------------------
// 0) tf32 pre-rounding, one launch
// ---------------------------------------------------------------------------
__global__ void round_all_kernel(const float* __restrict__ tfeat,
                                 const float* __restrict__ wq,
                                 const float* __restrict__ wk,
                                 const float* __restrict__ wv,
                                 const float* __restrict__ wp) {
    const int y = blockIdx.y;
    const float* src;
    float* dst;
    int n4;
    if (y == 0) { src = tfeat; dst = g_tf; n4 = BATCH * NT * DIM / 4; }
    else {
        src = (y == 1) ? wq : (y == 2) ? wk : (y == 3) ? wv : wp;
        dst = g_w + (size_t)(y - 1) * DIM * DIM;
        n4 = DIM * DIM / 4;
    }
    for (int i = blockIdx.x * blockDim.x + threadIdx.x; i < n4;
         i += gridDim.x * blockDim.x) {
        float4 v = ((const float4*)src)[i];
        v.x = round_tf(v.x); v.y = round_tf(v.y);
        v.z = round_tf(v.z); v.w = round_tf(v.w);
        ((float4*)dst)[i] = v;
    }
}

// ---------------------------------------------------------------------------
// 1) QKV projection, 3-stage cp.async pipeline. grid (6, 64, 3).
//    smem: A buffers 3x4608 w, B buffers at 13824 + 3x4608 w -> 110592 B.
// ---------------------------------------------------------------------------
__global__ __launch_bounds__(256, 2) void qkv_gemm_kernel(
    const float* __restrict__ bq, const float* __restrict__ bk,
    const float* __restrict__ bv)
{
    extern __shared__ uint32_t sm[];
    const uint32_t sbase = (uint32_t)__cvta_generic_to_shared(sm);

    const int z = blockIdx.z;
    const float* A = g_tf;
    const float* W = g_w + (size_t)z * DIM * DIM;
    const float* bias = (z == 0) ? bq : (z == 1) ? bk : bv;
    float* out = (z == 0) ? g_q : (z == 1) ? g_k : g_v;

    const int tid = threadIdx.x;
    const int lane = tid & 31;
    const int wid = tid >> 5;
    const int wm = wid >> 2, wn = wid & 3;
    const int m0 = blockIdx.y * 128;
    const int n0 = blockIdx.x * 128;

    const int srow = tid >> 3;
    const int skq = (tid & 7) << 2;

    auto stage = [&](int buf, int k0) {
        uint32_t aofs = sbase + (uint32_t)(buf * 4608) * 4;
        uint32_t bofs = sbase + (uint32_t)(13824 + buf * 4608) * 4;
#pragma unroll
        for (int u = 0; u < 4; ++u) {
            int row = srow + u * 32;
            cp16(aofs + (uint32_t)(row * 36 + skq) * 4, &A[(size_t)(m0 + row) * DIM + k0 + skq]);
            cp16(bofs + (uint32_t)(row * 36 + skq) * 4, &W[(size_t)(n0 + row) * DIM + k0 + skq]);
        }
        cp_commit();
    };

    float acc[4][4][4] = {};
    stage(0, 0);
    stage(1, 32);
    for (int kt = 0; kt < 24; ++kt) {
        if (kt + 2 < 24) { stage((kt + 2) % 3, (kt + 2) * 32); cp_wait<2>(); }
        else if (kt + 1 < 24) cp_wait<1>();
        else cp_wait<0>();
        __syncthreads();
        const uint32_t* As = sm + (kt % 3) * 4608;
        const uint32_t* Bs = sm + 13824 + (kt % 3) * 4608;
        compute_tiles<36, 4>(As, Bs, wm, wn, lane, acc);
        __syncthreads();
    }

#pragma unroll
    for (int mt = 0; mt < 4; ++mt) {
        int row = m0 + wm * 64 + mt * 16 + (lane >> 2);
        int b0i = row >> 10, t0 = row & 1023;
#pragma unroll
        for (int nt = 0; nt < 4; ++nt) {
            int col = n0 + wn * 32 + nt * 8 + ((lane & 3) << 1);
            int h = col >> 6, d = col & 63;
            float bx = bias[col], by = bias[col + 1];
            float2 lo = make_float2(round_tf(acc[mt][nt][0] + bx), round_tf(acc[mt][nt][1] + by));
            float2 hi = make_float2(round_tf(acc[mt][nt][2] + bx), round_tf(acc[mt][nt][3] + by));
            *(float2*)&out[((size_t)(b0i * NH + h) * NT + t0) * HD + d] = lo;
            *(float2*)&out[((size_t)(b0i * NH + h) * NT + t0 + 8) * HD + d] = hi;
        }
    }
}

// ---------------------------------------------------------------------------
// 2) S = exp(Q K^T * SCALE) + row-sum partials. grid (8, 8, 96).
// ---------------------------------------------------------------------------
__global__ __launch_bounds__(256, 2) void s_exp_kernel(float* __restrict__ attn)
{
    extern __shared__ uint32_t sm[];
    __shared__ float redsum[4][128];
    const uint32_t sbase = (uint32_t)__cvta_generic_to_shared(sm);

    const int tid = threadIdx.x;
    const int lane = tid & 31;
    const int wid = tid >> 5;
    const int wm = wid >> 2, wn = wid & 3;
    const int bh = blockIdx.z;
    const int m0 = blockIdx.y * 128;
    const int n0 = blockIdx.x * 128;

    const float* Q = g_q + (size_t)bh * NT * HD;
    const float* K = g_k + (size_t)bh * NT * HD;

    {
        const uint32_t kofs = sbase + (uint32_t)(128 * 68) * 4;
#pragma unroll
        for (int u = 0; u < 8; ++u) {
            int idx = tid + u * 256;
            int row = idx >> 4;
            int kq = (idx & 15) << 2;
            cp16(sbase + (uint32_t)(row * 68 + kq) * 4, &Q[(size_t)(m0 + row) * HD + kq]);
            cp16(kofs + (uint32_t)(row * 68 + kq) * 4, &K[(size_t)(n0 + row) * HD + kq]);
        }
        cp_commit();
        cp_wait<0>();
        __syncthreads();
    }

    float acc[4][4][4] = {};
    compute_tiles<68, 8>(sm, sm + 128 * 68, wm, wn, lane, acc);

    float rsum[4][2] = {};
    float* ap = attn + (size_t)bh * NT * NT;
#pragma unroll
    for (int mt = 0; mt < 4; ++mt) {
        int row = m0 + wm * 64 + mt * 16 + (lane >> 2);
#pragma unroll
        for (int nt = 0; nt < 4; ++nt) {
            int col = n0 + wn * 32 + nt * 8 + ((lane & 3) << 1);
            float e0 = __expf(acc[mt][nt][0] * SCALE);
            float e1 = __expf(acc[mt][nt][1] * SCALE);
            float e2 = __expf(acc[mt][nt][2] * SCALE);
            float e3 = __expf(acc[mt][nt][3] * SCALE);
            __stcs((float2*)&ap[(size_t)row * NT + col], make_float2(e0, e1));
            __stcs((float2*)&ap[(size_t)(row + 8) * NT + col], make_float2(e2, e3));
            rsum[mt][0] += e0 + e1;
            rsum[mt][1] += e2 + e3;
        }
    }
#pragma unroll
    for (int off = 1; off < 4; off <<= 1)
#pragma unroll
        for (int mt = 0; mt < 4; ++mt) {
            rsum[mt][0] += __shfl_xor_sync(0xffffffffu, rsum[mt][0], off);
            rsum[mt][1] += __shfl_xor_sync(0xffffffffu, rsum[mt][1], off);
        }
    if ((lane & 3) == 0) {
#pragma unroll
        for (int mt = 0; mt < 4; ++mt) {
            int r = wm * 64 + mt * 16 + (lane >> 2);
            redsum[wn][r] = rsum[mt][0];
            redsum[wn][r + 8] = rsum[mt][1];
        }
    }
    __syncthreads();
    if (tid < 128) {
        float s = redsum[0][tid] + redsum[1][tid] + redsum[2][tid] + redsum[3][tid];
        g_psum[((size_t)bh * NT + m0 + tid) * 8 + blockIdx.x] = s;
    }
}

// ---------------------------------------------------------------------------
// 3) O = P V with in-place normalization. grid (8, 96).
//    Block 128x64, warps 4x2, warp tile 32x32. smem 55296 B.
// ---------------------------------------------------------------------------
__global__ __launch_bounds__(256, 2) void pv_kernel(float* __restrict__ attn)
{
    extern __shared__ uint32_t sm[];
    __shared__ float invs[128];
    const uint32_t sbase = (uint32_t)__cvta_generic_to_shared(sm);

    const int tid = threadIdx.x;
    const int lane = tid & 31;
    const int wid = tid >> 5;
    const int wm = wid >> 1, wn = wid & 1;
    const int m0 = blockIdx.x * 128;
    const int bh = blockIdx.y;

    for (int r = tid; r < 128; r += 256) {
        const float* pp = &g_psum[((size_t)bh * NT + m0 + r) * 8];
        invs[r] = 1.0f / (pp[0] + pp[1] + pp[2] + pp[3] + pp[4] + pp[5] + pp[6] + pp[7]);
    }
    __syncthreads();

    const int srow = tid >> 3;
    const int skq = (tid & 7) << 2;
    float myinv[4];
#pragma unroll
    for (int u = 0; u < 4; ++u) myinv[u] = invs[srow + u * 32];

    float* Pg = attn + (size_t)bh * NT * NT;
    const float* V = g_v + (size_t)bh * NT * HD;

    const int vd = tid & 63;
    const int vk = tid >> 6;

    auto stageV = [&](int buf, int k0) {
        uint32_t vofs = sbase + (uint32_t)(9216 + buf * 2304) * 4;
#pragma unroll
        for (int u = 0; u < 8; ++u) {
            int k = vk + u * 4;
            cp4(vofs + (uint32_t)(vd * 36 + k) * 4, &V[(size_t)(k0 + k) * HD + vd]);
        }
        cp_commit();
    };

    float4 pf[4], pf2[4];
#pragma unroll
    for (int u = 0; u < 4; ++u)
        pf[u] = __ldcs((const float4*)&Pg[(size_t)(m0 + srow + u * 32) * NT + skq]);
    stageV(0, 0);

    float acc[2][4][4] = {};
    for (int kt = 0; kt < 32; ++kt) {
        const int cur = kt & 1;
        uint32_t* Pb = sm + cur * 4608;
        float4 vn[4];
#pragma unroll
        for (int u = 0; u < 4; ++u) {
            int row = srow + u * 32;
            float4 v = pf[u];
            v.x *= myinv[u]; v.y *= myinv[u]; v.z *= myinv[u]; v.w *= myinv[u];
            vn[u] = v;
            uint4 t;
            t.x = f2tf(v.x); t.y = f2tf(v.y); t.z = f2tf(v.z); t.w = f2tf(v.w);
            *(uint4*)&Pb[row * 36 + skq] = t;
        }
#pragma unroll
        for (int u = 0; u < 4; ++u) {
            int row = srow + u * 32;
            __stcs((float4*)&Pg[(size_t)(m0 + row) * NT + kt * 32 + skq], vn[u]);
        }
        if (kt + 1 < 32) {
            stageV((kt + 1) & 1, (kt + 1) * 32);
#pragma unroll
            for (int u = 0; u < 4; ++u)
                pf2[u] = __ldcs((const float4*)&Pg[(size_t)(m0 + srow + u * 32) * NT + (kt + 1) * 32 + skq]);
            cp_wait<1>();
        } else {
            cp_wait<0>();
        }
        __syncthreads();

        const uint32_t* Ps = sm + cur * 4608;
        const uint32_t* Vs = sm + 9216 + cur * 2304;
#pragma unroll
        for (int ks = 0; ks < 4; ++ks) {
            const int col = ks * 8 + (lane & 3);
            uint32_t a[2][4], b[4][2];
#pragma unroll
            for (int mt = 0; mt < 2; ++mt) {
                int r = wm * 32 + mt * 16 + (lane >> 2);
                a[mt][0] = Ps[r * 36 + col];
                a[mt][1] = Ps[(r + 8) * 36 + col];
                a[mt][2] = Ps[r * 36 + col + 4];
                a[mt][3] = Ps[(r + 8) * 36 + col + 4];
            }
#pragma unroll
            for (int nt = 0; nt < 4; ++nt) {
                int n = wn * 32 + nt * 8 + (lane >> 2);
                b[nt][0] = Vs[n * 36 + col];
                b[nt][1] = Vs[n * 36 + col + 4];
            }
#pragma unroll
            for (int mt = 0; mt < 2; ++mt)
#pragma unroll
                for (int nt = 0; nt < 4; ++nt)
                    mma8(acc[mt][nt], a[mt][0], a[mt][1], a[mt][2], a[mt][3],
                         b[nt][0], b[nt][1]);
        }
        __syncthreads();
#pragma unroll
        for (int u = 0; u < 4; ++u) pf[u] = pf2[u];
    }

    const int b = bh / NH, h = bh % NH;
#pragma unroll
    for (int mt = 0; mt < 2; ++mt) {
        int row = m0 + wm * 32 + mt * 16 + (lane >> 2);
#pragma unroll
        for (int nt = 0; nt < 4; ++nt) {
            int d = wn * 32 + nt * 8 + ((lane & 3) << 1);
            *(float2*)&g_x[((size_t)b * NT + row) * DIM + h * HD + d] =
                make_float2(round_tf(acc[mt][nt][0]), round_tf(acc[mt][nt][1]));
            *(float2*)&g_x[((size_t)b * NT + row + 8) * DIM + h * HD + d] =
                make_float2(round_tf(acc[mt][nt][2]), round_tf(acc[mt][nt][3]));
        }
    }
}

// ---------------------------------------------------------------------------
// 4) output projection, 3-stage cp.async pipeline. grid (6, 64).
// ---------------------------------------------------------------------------
__global__ __launch_bounds__(256, 2) void proj_gemm_kernel(
    const float* __restrict__ bias, float* __restrict__ out)
{
    extern __shared__ uint32_t sm[];
    const uint32_t sbase = (uint32_t)__cvta_generic_to_shared(sm);

    const float* A = g_x;
    const float* W = g_w + (size_t)3 * DIM * DIM;

    const int tid = threadIdx.x;
    const int lane = tid & 31;
    const int wid = tid >> 5;
    const int wm = wid >> 2, wn = wid & 3;
    const int m0 = blockIdx.y * 128;
    const int n0 = blockIdx.x * 128;

    const int srow = tid >> 3;
    const int skq = (tid & 7) << 2;

    auto stage = [&](int buf, int k0) {
        uint32_t aofs = sbase + (uint32_t)(buf * 4608) * 4;
        uint32_t bofs = sbase + (uint32_t)(13824 + buf * 4608) * 4;
#pragma unroll
        for (int u = 0; u < 4; ++u) {
            int row = srow + u * 32;
            cp16(aofs + (uint32_t)(row * 36 + skq) * 4, &A[(size_t)(m0 + row) * DIM + k0 + skq]);
            cp16(bofs + (uint32_t)(row * 36 + skq) * 4, &W[(size_t)(n0 + row) * DIM + k0 + skq]);
        }
        cp_commit();
    };

    float acc[4][4][4] = {};
    stage(0, 0);
    stage(1, 32);
    for (int kt = 0; kt < 24; ++kt) {
        if (kt + 2 < 24) { stage((kt + 2) % 3, (kt + 2) * 32); cp_wait<2>(); }
        else if (kt + 1 < 24) cp_wait<1>();
        else cp_wait<0>();
        __syncthreads();
        const uint32_t* As = sm + (kt % 3) * 4608;
        const uint32_t* Bs = sm + 13824 + (kt % 3) * 4608;
        compute_tiles<36, 4>(As, Bs, wm, wn, lane, acc);
        __syncthreads();
    }

#pragma unroll
    for (int mt = 0; mt < 4; ++mt) {
        int row = m0 + wm * 64 + mt * 16 + (lane >> 2);
#pragma unroll
        for (int nt = 0; nt < 4; ++nt) {
            int col = n0 + wn * 32 + nt * 8 + ((lane & 3) << 1);
            float bx = bias[col], by = bias[col + 1];
            *(float2*)&out[(size_t)row * DIM + col] =
                make_float2(acc[mt][nt][0] + bx, acc[mt][nt][1] + by);
            *(float2*)&out[(size_t)(row + 8) * DIM + col] =
                make_float2(acc[mt][nt][2] + bx, acc[mt][nt][3] + by);
        }
    }
}

// ---------------------------------------------------------------------------

extern "C" void kernel_launch(void* const* d_in, const int* in_sizes, int n_in,
                              void* d_out, int out_size)
{
    const float* tfeat = (const float*)d_in[0];
    const float* wq = (const float*)d_in[1];
    const float* bq = (const float*)d_in[2];
    const float* wk = (const float*)d_in[3];
    const float* bk = (const float*)d_in[4];
    const float* wv = (const float*)d_in[5];
    const float* bv = (const float*)d_in[6];
    const float* wp = (const float*)d_in[7];
    const float* bp = (const float*)d_in[8];

    float* xout = (float*)d_out;
    float* attn_out = (float*)d_out + (size_t)BATCH * NT * DIM;

    round_all_kernel<<<dim3(1024, 5), 256>>>(tfeat, wq, wk, wv, wp);

    cudaFuncSetAttribute(qkv_gemm_kernel, cudaFuncAttributeMaxDynamicSharedMemorySize, 110592);
    cudaFuncSetAttribute(s_exp_kernel, cudaFuncAttributeMaxDynamicSharedMemorySize, 69632);
    cudaFuncSetAttribute(pv_kernel, cudaFuncAttributeMaxDynamicSharedMemorySize, 55296);
    cudaFuncSetAttribute(proj_gemm_kernel, cudaFuncAttributeMaxDynamicSharedMemorySize, 110592);

    qkv_gemm_kernel<<<dim3(DIM / 128, (BATCH * NT) / 128, 3), 256, 110592>>>(bq, bk, bv);
    s_exp_kernel<<<dim3(NT / 128, NT / 128, NBH), 256, 69632>>>(attn_out);
    pv_kernel<<<dim3(NT / 128, NBH), 256, 55296>>>(attn_out);
    proj_gemm_kernel<<<dim3(DIM / 128, (BATCH * NT) / 128), 256, 110592>>>(bp, xout);
}